// round 13
// baseline (speedup 1.0000x reference)
#include <cuda_runtime.h>
#include <math.h>

#define NA 5000
#define NE 100000
#define FF 128
#define NB 20
#define CUTOFF 5.0f

// ---------------- device scratch (no allocations allowed) ----------------
__device__ float g_s[NA * FF];
__device__ float g_v[NA * 3 * FF];
__device__ float g_vold[NA * 3 * FF];
__device__ float g_phi[NA * 3 * FF];
__device__ float g_h[NA * FF];
__device__ float g_Uv[NA * 3 * FF];
__device__ float g_Vv[NA * 3 * FF];
__device__ float g_cat[NA * 2 * FF];
__device__ float g_a[NA * 3 * FF];

// compacted edge arrays (valid edges only)
__device__ int    g_nval;
__device__ int2   g_ce_idx[NE];   // (dst, src)
__device__ float4 g_ce_u[NE];     // (u0, u1, u2, env)
__device__ float2 g_ce_tr[NE];    // (s1*inv, 2*cos(x))

#define BUF_S   0
#define BUF_H   1
#define BUF_PHI 2
#define BUF_V   3
#define BUF_UV  4
#define BUF_VV  5
#define BUF_CAT 6
#define BUF_A   7

__device__ __forceinline__ float* buf_ptr(int b) {
    switch (b) {
        case BUF_S:   return g_s;
        case BUF_H:   return g_h;
        case BUF_PHI: return g_phi;
        case BUF_V:   return g_v;
        case BUF_UV:  return g_Uv;
        case BUF_VV:  return g_Vv;
        case BUF_CAT: return g_cat;
        default:      return g_a;
    }
}

__device__ __forceinline__ float silu_f(float x) {
    return x / (1.0f + __expf(-x));
}

// ---- packed fp32x2 helpers ----
__device__ __forceinline__ unsigned long long dup2(float x) {
    unsigned long long r;
    asm("mov.b64 %0, {%1, %1};" : "=l"(r) : "f"(x));
    return r;
}
__device__ __forceinline__ void fma2(unsigned long long& acc, unsigned long long a,
                                     unsigned long long b) {
    asm("fma.rn.f32x2 %0, %1, %2, %0;" : "+l"(acc) : "l"(a), "l"(b));
}
__device__ __forceinline__ void unpack2(unsigned long long p, float& lo, float& hi) {
    asm("mov.b64 {%0, %1}, %2;" : "=f"(lo), "=f"(hi) : "l"(p));
}
__device__ __forceinline__ void red_add_v4(float* p, float4 v) {
    asm volatile("red.global.add.v4.f32 [%0], {%1, %2, %3, %4};"
                 :: "l"(p), "f"(v.x), "f"(v.y), "f"(v.z), "f"(v.w) : "memory");
}

// ---------------- init ----------------
__global__ void init_kernel(const float* __restrict__ emb, const int* __restrict__ Z) {
    int idx = blockIdx.x * blockDim.x + threadIdx.x;
    if (idx == 0) g_nval = 0;
    if (idx < NA * 3 * FF) {
        g_v[idx] = 0.0f;
        g_vold[idx] = 0.0f;
    }
    if (idx < NA * FF) {
        int n = idx >> 7;
        int f = idx & 127;
        g_s[idx] = emb[Z[n] * FF + f];
    }
}

// ---------------- compact valid edges + precompute ----------------
__global__ void compact_kernel(const int* __restrict__ eidx, const float* __restrict__ edist,
                               const float* __restrict__ ediff) {
    int e = blockIdx.x * blockDim.x + threadIdx.x;
    if (e >= NE) return;
    float dist = edist[e];
    if (dist >= CUTOFF) return;
    int slot = atomicAdd(&g_nval, 1);
    float inv = 1.0f / dist;
    float x = dist * (3.14159265358979323846f / CUTOFF);
    float s1, c1;
    __sincosf(x, &s1, &c1);
    g_ce_idx[slot] = make_int2(eidx[2 * e], eidx[2 * e + 1]);
    g_ce_u[slot] = make_float4(ediff[3 * e] * inv, ediff[3 * e + 1] * inv,
                               ediff[3 * e + 2] * inv, 0.5f * (c1 + 1.0f));
    g_ce_tr[slot] = make_float2(s1 * inv, 2.0f * c1);
}

// ---------------- SGEMM 64x64x16: M-pair packed, conflict-free B, dbl-buffered ----------------
// Used for ALL dense layers. For N=384 the grid is (6, 79) = 474 CTAs (~3.2/SM,
// fills the 3-CTA register budget; the BM=128 variant left SMs half-empty at 240 CTAs).
template <int ACT>
__global__ void __launch_bounds__(256)
sgemm64_kernel(int abuf, const float* __restrict__ B,
               const float* __restrict__ bias, int cbuf,
               int M, int N, int K) {
    const float* A = buf_ptr(abuf);
    float* C = buf_ptr(cbuf);

    const int BM = 64, BN = 64, BK = 16;
    __shared__ float As[2][BK][BM + 4];
    __shared__ float Bs[2][BK][BN];

    int tid = threadIdx.x;
    int tx = tid & 15;
    int ty = tid >> 4;
    int row0 = blockIdx.y * BM;
    int col0 = blockIdx.x * BN;

    int ar = tid >> 2;
    int ac = (tid & 3) * 4;
    int br = tid >> 4;
    int bc = (tid & 15) * 4;

    bool va = (row0 + ar) < M;
    const float* Ap = A + (size_t)(row0 + ar) * K + ac;
    const float* Bp = B + (size_t)br * N + col0 + bc;

    unsigned long long acc[2][4];
#pragma unroll
    for (int p = 0; p < 2; p++)
#pragma unroll
        for (int c = 0; c < 4; c++) acc[p][c] = 0ull;

    const float4 fz = make_float4(0.f, 0.f, 0.f, 0.f);
    float4 a0 = va ? *(const float4*)Ap : fz;
    float4 b0 = *(const float4*)Bp;

    As[0][ac + 0][ar] = a0.x; As[0][ac + 1][ar] = a0.y;
    As[0][ac + 2][ar] = a0.z; As[0][ac + 3][ar] = a0.w;
    *(float4*)&Bs[0][br][bc] = b0;

    int nIter = K / BK;
    for (int it = 0; it < nIter; it++) {
        __syncthreads();
        int cur = it & 1;
        if (it + 1 < nIter) {
            int kn = (it + 1) * BK;
            a0 = va ? *(const float4*)(Ap + kn) : fz;
            b0 = *(const float4*)(Bp + (size_t)kn * N);
        }

#pragma unroll
        for (int kk = 0; kk < BK; kk++) {
            ulonglong2 ap = *(const ulonglong2*)&As[cur][kk][ty * 4];
            float4 bf = *(const float4*)&Bs[cur][kk][tx * 4];
            unsigned long long bd0 = dup2(bf.x);
            unsigned long long bd1 = dup2(bf.y);
            unsigned long long bd2 = dup2(bf.z);
            unsigned long long bd3 = dup2(bf.w);
            fma2(acc[0][0], ap.x, bd0); fma2(acc[0][1], ap.x, bd1);
            fma2(acc[0][2], ap.x, bd2); fma2(acc[0][3], ap.x, bd3);
            fma2(acc[1][0], ap.y, bd0); fma2(acc[1][1], ap.y, bd1);
            fma2(acc[1][2], ap.y, bd2); fma2(acc[1][3], ap.y, bd3);
        }

        if (it + 1 < nIter) {
            int nxt = (it + 1) & 1;
            As[nxt][ac + 0][ar] = a0.x; As[nxt][ac + 1][ar] = a0.y;
            As[nxt][ac + 2][ar] = a0.z; As[nxt][ac + 3][ar] = a0.w;
            *(float4*)&Bs[nxt][br][bc] = b0;
        }
    }

    int c0 = col0 + tx * 4;
    float4 bv = make_float4(0.f, 0.f, 0.f, 0.f);
    if (bias) bv = *(const float4*)&bias[c0];
#pragma unroll
    for (int p = 0; p < 2; p++) {
        int r0 = row0 + ty * 4 + 2 * p;
        float lo[4], hi[4];
#pragma unroll
        for (int c = 0; c < 4; c++) unpack2(acc[p][c], lo[c], hi[c]);
        if (r0 < M) {
            float4 o = make_float4(lo[0] + bv.x, lo[1] + bv.y, lo[2] + bv.z, lo[3] + bv.w);
            if (ACT == 1) { o.x = silu_f(o.x); o.y = silu_f(o.y); o.z = silu_f(o.z); o.w = silu_f(o.w); }
            *(float4*)&C[(size_t)r0 * N + c0] = o;
        }
        if (r0 + 1 < M) {
            float4 o = make_float4(hi[0] + bv.x, hi[1] + bv.y, hi[2] + bv.z, hi[3] + bv.w);
            if (ACT == 1) { o.x = silu_f(o.x); o.y = silu_f(o.y); o.z = silu_f(o.z); o.w = silu_f(o.w); }
            *(float4*)&C[(size_t)(r0 + 1) * N + c0] = o;
        }
    }
}

// ---------------- dual-B SGEMM (BM=64): Uv = v@U, Vv = v@V ----------------
__global__ void __launch_bounds__(256)
sgemm_uv_kernel(const float* __restrict__ B1, const float* __restrict__ B2) {
    const float* A = g_v;
    const int M = NA * 3, N = FF, K = FF;
    const int BM = 64, BN = 64, BK = 16;
    __shared__ float As[2][BK][BM + 4];
    __shared__ float Bs1[2][BK][BN];
    __shared__ float Bs2[2][BK][BN];

    int tid = threadIdx.x;
    int tx = tid & 15;
    int ty = tid >> 4;
    int row0 = blockIdx.y * BM;
    int col0 = blockIdx.x * BN;

    int ar = tid >> 2;
    int ac = (tid & 3) * 4;
    int br = tid >> 4;
    int bc = (tid & 15) * 4;

    bool va = (row0 + ar) < M;
    const float* Ap = A + (size_t)(row0 + ar) * K + ac;
    const float* Bp1 = B1 + (size_t)br * N + col0 + bc;
    const float* Bp2 = B2 + (size_t)br * N + col0 + bc;

    unsigned long long accU[2][4], accV[2][4];
#pragma unroll
    for (int p = 0; p < 2; p++)
#pragma unroll
        for (int c = 0; c < 4; c++) { accU[p][c] = 0ull; accV[p][c] = 0ull; }

    const float4 fz = make_float4(0.f, 0.f, 0.f, 0.f);
    float4 a0 = va ? *(const float4*)Ap : fz;
    float4 b1 = *(const float4*)Bp1;
    float4 b2 = *(const float4*)Bp2;

    As[0][ac + 0][ar] = a0.x; As[0][ac + 1][ar] = a0.y;
    As[0][ac + 2][ar] = a0.z; As[0][ac + 3][ar] = a0.w;
    *(float4*)&Bs1[0][br][bc] = b1;
    *(float4*)&Bs2[0][br][bc] = b2;

    const int nIter = K / BK;
    for (int it = 0; it < nIter; it++) {
        __syncthreads();
        int cur = it & 1;
        if (it + 1 < nIter) {
            int kn = (it + 1) * BK;
            a0 = va ? *(const float4*)(Ap + kn) : fz;
            b1 = *(const float4*)(Bp1 + (size_t)kn * N);
            b2 = *(const float4*)(Bp2 + (size_t)kn * N);
        }

#pragma unroll
        for (int kk = 0; kk < BK; kk++) {
            ulonglong2 ap = *(const ulonglong2*)&As[cur][kk][ty * 4];
            float4 uf = *(const float4*)&Bs1[cur][kk][tx * 4];
            float4 vf = *(const float4*)&Bs2[cur][kk][tx * 4];
            unsigned long long u0 = dup2(uf.x), u1 = dup2(uf.y), u2 = dup2(uf.z), u3 = dup2(uf.w);
            unsigned long long v0 = dup2(vf.x), v1 = dup2(vf.y), v2 = dup2(vf.z), v3 = dup2(vf.w);
            fma2(accU[0][0], ap.x, u0); fma2(accU[0][1], ap.x, u1);
            fma2(accU[0][2], ap.x, u2); fma2(accU[0][3], ap.x, u3);
            fma2(accU[1][0], ap.y, u0); fma2(accU[1][1], ap.y, u1);
            fma2(accU[1][2], ap.y, u2); fma2(accU[1][3], ap.y, u3);
            fma2(accV[0][0], ap.x, v0); fma2(accV[0][1], ap.x, v1);
            fma2(accV[0][2], ap.x, v2); fma2(accV[0][3], ap.x, v3);
            fma2(accV[1][0], ap.y, v0); fma2(accV[1][1], ap.y, v1);
            fma2(accV[1][2], ap.y, v2); fma2(accV[1][3], ap.y, v3);
        }

        if (it + 1 < nIter) {
            int nxt = (it + 1) & 1;
            As[nxt][ac + 0][ar] = a0.x; As[nxt][ac + 1][ar] = a0.y;
            As[nxt][ac + 2][ar] = a0.z; As[nxt][ac + 3][ar] = a0.w;
            *(float4*)&Bs1[nxt][br][bc] = b1;
            *(float4*)&Bs2[nxt][br][bc] = b2;
        }
    }

    int c0 = col0 + tx * 4;
#pragma unroll
    for (int p = 0; p < 2; p++) {
        int r0 = row0 + ty * 4 + 2 * p;
        float ulo[4], uhi[4], vlo[4], vhi[4];
#pragma unroll
        for (int c = 0; c < 4; c++) {
            unpack2(accU[p][c], ulo[c], uhi[c]);
            unpack2(accV[p][c], vlo[c], vhi[c]);
        }
        if (r0 < M) {
            *(float4*)&g_Uv[(size_t)r0 * N + c0] = make_float4(ulo[0], ulo[1], ulo[2], ulo[3]);
            *(float4*)&g_Vv[(size_t)r0 * N + c0] = make_float4(vlo[0], vlo[1], vlo[2], vlo[3]);
        }
        if (r0 + 1 < M) {
            *(float4*)&g_Uv[(size_t)(r0 + 1) * N + c0] = make_float4(uhi[0], uhi[1], uhi[2], uhi[3]);
            *(float4*)&g_Vv[(size_t)(r0 + 1) * N + c0] = make_float4(vhi[0], vhi[1], vhi[2], vhi[3]);
        }
    }
}

// ---------------- edge message kernel (unchanged) ----------------
__global__ void __launch_bounds__(256, 2)
edge_kernel(const float* __restrict__ fw, const float* __restrict__ fb) {
    __shared__ float sfw[NB * 384];
    __shared__ float sfb[384];
    for (int i = threadIdx.x; i < NB * 384; i += blockDim.x) sfw[i] = fw[i];
    for (int i = threadIdx.x; i < 384; i += blockDim.x) sfb[i] = fb[i];
    __syncthreads();

    int lane = threadIdx.x & 31;
    int gw = (blockIdx.x * blockDim.x + threadIdx.x) >> 5;
    int nw = (gridDim.x * blockDim.x) >> 5;
    int nval = g_nval;

    ulonglong2 bg[3];
#pragma unroll
    for (int g = 0; g < 3; g++) bg[g] = *(const ulonglong2*)&sfb[g * 128 + 4 * lane];

    for (int e0 = gw * 4; e0 < nval; e0 += nw * 4) {
        int cnt = nval - e0;
        if (cnt > 4) cnt = 4;

        int dst[4], src[4];
        float4 ue[4];
        float sp[4], sc[4], twoc[4];
#pragma unroll
        for (int j = 0; j < 4; j++) {
            int e = (j < cnt) ? e0 + j : e0;
            int2 ij = g_ce_idx[e];
            dst[j] = ij.x;
            src[j] = ij.y;
            ue[j] = g_ce_u[e];
            float2 tg = g_ce_tr[e];
            sp[j] = 0.0f;
            sc[j] = tg.x;
            twoc[j] = tg.y;
        }

        ulonglong2 acc[4][3];
#pragma unroll
        for (int j = 0; j < 4; j++)
#pragma unroll
            for (int g = 0; g < 3; g++) acc[j][g] = bg[g];

#pragma unroll
        for (int b = 0; b < NB; b++) {
            ulonglong2 w0 = *(const ulonglong2*)&sfw[b * 384 + 0 * 128 + 4 * lane];
            ulonglong2 w1 = *(const ulonglong2*)&sfw[b * 384 + 1 * 128 + 4 * lane];
            ulonglong2 w2 = *(const ulonglong2*)&sfw[b * 384 + 2 * 128 + 4 * lane];
#pragma unroll
            for (int j = 0; j < 4; j++) {
                float r = sc[j];
                float sn = twoc[j] * sc[j] - sp[j];
                sp[j] = sc[j];
                sc[j] = sn;
                unsigned long long rd = dup2(r);
                fma2(acc[j][0].x, rd, w0.x);
                fma2(acc[j][0].y, rd, w0.y);
                fma2(acc[j][1].x, rd, w1.x);
                fma2(acc[j][1].y, rd, w1.y);
                fma2(acc[j][2].x, rd, w2.x);
                fma2(acc[j][2].y, rd, w2.y);
            }
        }

#pragma unroll
        for (int j = 0; j < 4; j++) {
            if (j >= cnt) break;
            float ej = ue[j].w;
            float f0[4], f1[4], f2[4];
            unpack2(acc[j][0].x, f0[0], f0[1]);
            unpack2(acc[j][0].y, f0[2], f0[3]);
            unpack2(acc[j][1].x, f1[0], f1[1]);
            unpack2(acc[j][1].y, f1[2], f1[3]);
            unpack2(acc[j][2].x, f2[0], f2[1]);
            unpack2(acc[j][2].y, f2[2], f2[3]);

            const float4* ph4 = (const float4*)(g_phi + (size_t)src[j] * 384);
            const float4* vs4 = (const float4*)(g_vold + (size_t)src[j] * 384);
            float4 pA = ph4[lane];
            float4 pB = ph4[lane + 32];
            float4 pC = ph4[lane + 64];
            float4 vA = vs4[lane];
            float4 vB = vs4[lane + 32];
            float4 vC = vs4[lane + 64];

            float4 gsv, gev, ms;
            gsv.x = f0[0] * ej * pA.x; gsv.y = f0[1] * ej * pA.y;
            gsv.z = f0[2] * ej * pA.z; gsv.w = f0[3] * ej * pA.w;
            gev.x = f1[0] * ej * pB.x; gev.y = f1[1] * ej * pB.y;
            gev.z = f1[2] * ej * pB.z; gev.w = f1[3] * ej * pB.w;
            ms.x = f2[0] * ej * pC.x; ms.y = f2[1] * ej * pC.y;
            ms.z = f2[2] * ej * pC.z; ms.w = f2[3] * ej * pC.w;

            float* sd = g_s + (size_t)dst[j] * 128 + 4 * lane;
            float* vd = g_v + (size_t)dst[j] * 384 + 4 * lane;
            red_add_v4(sd, ms);

            float u0 = ue[j].x, u1 = ue[j].y, u2 = ue[j].z;
            float4 m0, m1, m2;
            m0.x = vA.x * gsv.x + gev.x * u0; m0.y = vA.y * gsv.y + gev.y * u0;
            m0.z = vA.z * gsv.z + gev.z * u0; m0.w = vA.w * gsv.w + gev.w * u0;
            m1.x = vB.x * gsv.x + gev.x * u1; m1.y = vB.y * gsv.y + gev.y * u1;
            m1.z = vB.z * gsv.z + gev.z * u1; m1.w = vB.w * gsv.w + gev.w * u1;
            m2.x = vC.x * gsv.x + gev.x * u2; m2.y = vC.y * gsv.y + gev.y * u2;
            m2.z = vC.z * gsv.z + gev.z * u2; m2.w = vC.w * gsv.w + gev.w * u2;
            red_add_v4(vd, m0);
            red_add_v4(vd + 128, m1);
            red_add_v4(vd + 256, m2);
        }
    }
}

// ---------------- Vn + concat ----------------
__global__ void vncat_kernel() {
    int idx = blockIdx.x * blockDim.x + threadIdx.x;
    if (idx >= NA * FF) return;
    int n = idx >> 7;
    int f = idx & 127;
    float q = 0.0f;
#pragma unroll
    for (int i = 0; i < 3; i++) {
        float d = g_Vv[(size_t)(n * 3 + i) * FF + f];
        q += d * d;
    }
    g_cat[(size_t)n * 256 + f] = g_s[idx];
    g_cat[(size_t)n * 256 + 128 + f] = sqrtf(q);
}

// ---------------- update ----------------
__global__ void update_kernel() {
    int idx = blockIdx.x * blockDim.x + threadIdx.x;
    if (idx >= NA * FF) return;
    int n = idx >> 7;
    int f = idx & 127;
    float avv = g_a[(size_t)n * 384 + f];
    float asv = g_a[(size_t)n * 384 + 128 + f];
    float ass = g_a[(size_t)n * 384 + 256 + f];
    float dot = 0.0f;
#pragma unroll
    for (int i = 0; i < 3; i++) {
        size_t vi = (size_t)(n * 3 + i) * FF + f;
        float uvi = g_Uv[vi];
        float vvi = g_Vv[vi];
        dot += uvi * vvi;
        float nv = g_v[vi] + avv * uvi;
        g_v[vi] = nv;
        g_vold[vi] = nv;
    }
    g_s[idx] += asv * dot + ass;
}

// ---------------- readout ----------------
__global__ void readout_kernel(const float* __restrict__ w1, const float* __restrict__ b1,
                               const float* __restrict__ w2, const float* __restrict__ b2,
                               float* __restrict__ out) {
    __shared__ float sw1[FF * 64];
    __shared__ float sw2[64];
    __shared__ float sb1[64];
    for (int i = threadIdx.x; i < FF * 64; i += blockDim.x) sw1[i] = w1[i];
    if (threadIdx.x < 64) {
        sw2[threadIdx.x] = w2[threadIdx.x];
        sb1[threadIdx.x] = b1[threadIdx.x];
    }
    __syncthreads();

    int wid = threadIdx.x >> 5;
    int lane = threadIdx.x & 31;
    for (int n = blockIdx.x * 8 + wid; n < NA; n += gridDim.x * 8) {
        const float* srow = g_s + (size_t)n * FF;
        float acc0 = sb1[lane];
        float acc1 = sb1[lane + 32];
        for (int f = 0; f < FF; f++) {
            float sv = srow[f];
            acc0 += sv * sw1[f * 64 + lane];
            acc1 += sv * sw1[f * 64 + lane + 32];
        }
        float r = silu_f(acc0) * sw2[lane] + silu_f(acc1) * sw2[lane + 32];
#pragma unroll
        for (int off = 16; off > 0; off >>= 1)
            r += __shfl_down_sync(0xFFFFFFFF, r, off);
        if (lane == 0) out[n] = r + b2[0];
    }
}

// ---------------- launch ----------------
extern "C" void kernel_launch(void* const* d_in, const int* in_sizes, int n_in,
                              void* d_out, int out_size) {
    const int* Z        = (const int*)d_in[0];
    const int* eidx     = (const int*)d_in[1];
    const float* ediff  = (const float*)d_in[2];
    const float* edist  = (const float*)d_in[3];
    const float* emb    = (const float*)d_in[4];
    const float* msg_w1 = (const float*)d_in[5];
    const float* msg_b1 = (const float*)d_in[6];
    const float* msg_w2 = (const float*)d_in[7];
    const float* msg_b2 = (const float*)d_in[8];
    const float* filt_w = (const float*)d_in[9];
    const float* filt_b = (const float*)d_in[10];
    const float* upd_U  = (const float*)d_in[11];
    const float* upd_V  = (const float*)d_in[12];
    const float* upd_w1 = (const float*)d_in[13];
    const float* upd_b1 = (const float*)d_in[14];
    const float* upd_w2 = (const float*)d_in[15];
    const float* upd_b2 = (const float*)d_in[16];
    const float* ro_w1  = (const float*)d_in[17];
    const float* ro_b1  = (const float*)d_in[18];
    const float* ro_w2  = (const float*)d_in[19];
    const float* ro_b2  = (const float*)d_in[20];
    float* out = (float*)d_out;

    const int EL3 = NA * 3 * FF;
    const int GY64 = (NA + 63) / 64;          // 79
    const int GYUV = (NA * 3 + 63) / 64;      // 235

    init_kernel<<<(EL3 + 255) / 256, 256>>>(emb, Z);
    compact_kernel<<<(NE + 255) / 256, 256>>>(eidx, edist, ediff);

    for (int l = 0; l < 3; l++) {
        sgemm64_kernel<1><<<dim3(2, GY64), 256>>>(
            BUF_S, msg_w1 + (size_t)l * FF * FF, msg_b1 + l * FF, BUF_H, NA, FF, FF);
        sgemm64_kernel<0><<<dim3(6, GY64), 256>>>(
            BUF_H, msg_w2 + (size_t)l * FF * 384, msg_b2 + l * 384, BUF_PHI, NA, 384, FF);

        edge_kernel<<<592, 256>>>(filt_w + (size_t)l * NB * 384, filt_b + l * 384);

        sgemm_uv_kernel<<<dim3(2, GYUV), 256>>>(
            upd_U + (size_t)l * FF * FF, upd_V + (size_t)l * FF * FF);

        vncat_kernel<<<(NA * FF + 255) / 256, 256>>>();

        sgemm64_kernel<1><<<dim3(2, GY64), 256>>>(
            BUF_CAT, upd_w1 + (size_t)l * 2 * FF * FF, upd_b1 + l * FF, BUF_H, NA, FF, 2 * FF);
        sgemm64_kernel<0><<<dim3(6, GY64), 256>>>(
            BUF_H, upd_w2 + (size_t)l * FF * 384, upd_b2 + l * 384, BUF_A, NA, 384, FF);

        update_kernel<<<(NA * FF + 255) / 256, 256>>>();
    }

    readout_kernel<<<148, 256>>>(ro_w1, ro_b1, ro_w2, ro_b2, out);
}

// round 15
// speedup vs baseline: 1.0830x; 1.0830x over previous
#include <cuda_runtime.h>
#include <math.h>

#define NA 5000
#define NE 100000
#define FF 128
#define NB 20
#define CUTOFF 5.0f

// ---------------- device scratch (no allocations allowed) ----------------
__device__ float g_s[NA * FF];
__device__ float g_v[NA * 3 * FF];
__device__ float g_vold[NA * 3 * FF];
__device__ float g_phi[NA * 3 * FF];
__device__ float g_h[NA * FF];
__device__ float g_Uv[NA * 3 * FF];
__device__ float g_Vv[NA * 3 * FF];
__device__ float g_cat[NA * 2 * FF];
__device__ float g_a[NA * 3 * FF];

// compacted edge arrays (valid edges only)
__device__ int    g_nval;
__device__ int2   g_ce_idx[NE];   // (dst, src)
__device__ float4 g_ce_u[NE];     // (u0, u1, u2, env)
__device__ float2 g_ce_tr[NE];    // (s1*inv, 2*cos(x))  — scaled sine recurrence seeds

#define BUF_S   0
#define BUF_H   1
#define BUF_PHI 2
#define BUF_V   3
#define BUF_UV  4
#define BUF_VV  5
#define BUF_CAT 6
#define BUF_A   7

__device__ __forceinline__ float* buf_ptr(int b) {
    switch (b) {
        case BUF_S:   return g_s;
        case BUF_H:   return g_h;
        case BUF_PHI: return g_phi;
        case BUF_V:   return g_v;
        case BUF_UV:  return g_Uv;
        case BUF_VV:  return g_Vv;
        case BUF_CAT: return g_cat;
        default:      return g_a;
    }
}

__device__ __forceinline__ float silu_f(float x) {
    return x / (1.0f + __expf(-x));
}

// ---- packed fp32x2 helpers ----
__device__ __forceinline__ unsigned long long dup2(float x) {
    unsigned long long r;
    asm("mov.b64 %0, {%1, %1};" : "=l"(r) : "f"(x));
    return r;
}
__device__ __forceinline__ void fma2(unsigned long long& acc, unsigned long long a,
                                     unsigned long long b) {
    asm("fma.rn.f32x2 %0, %1, %2, %0;" : "+l"(acc) : "l"(a), "l"(b));
}
__device__ __forceinline__ void unpack2(unsigned long long p, float& lo, float& hi) {
    asm("mov.b64 {%0, %1}, %2;" : "=f"(lo), "=f"(hi) : "l"(p));
}
__device__ __forceinline__ void red_add_v4(float* p, float4 v) {
    asm volatile("red.global.add.v4.f32 [%0], {%1, %2, %3, %4};"
                 :: "l"(p), "f"(v.x), "f"(v.y), "f"(v.z), "f"(v.w) : "memory");
}

// ---------------- init: s = emb[Z], v = vold = 0, nval = 0 ----------------
__global__ void init_kernel(const float* __restrict__ emb, const int* __restrict__ Z) {
    int idx = blockIdx.x * blockDim.x + threadIdx.x;
    if (idx == 0) g_nval = 0;
    if (idx < NA * 3 * FF) {
        g_v[idx] = 0.0f;
        g_vold[idx] = 0.0f;
    }
    if (idx < NA * FF) {
        int n = idx >> 7;
        int f = idx & 127;
        g_s[idx] = emb[Z[n] * FF + f];
    }
}

// ---------------- compact valid edges + precompute trig/unit/env ----------------
__global__ void compact_kernel(const int* __restrict__ eidx, const float* __restrict__ edist,
                               const float* __restrict__ ediff) {
    int e = blockIdx.x * blockDim.x + threadIdx.x;
    if (e >= NE) return;
    float dist = edist[e];
    if (dist >= CUTOFF) return;
    int slot = atomicAdd(&g_nval, 1);
    float inv = 1.0f / dist;
    float x = dist * (3.14159265358979323846f / CUTOFF);
    float s1, c1;
    __sincosf(x, &s1, &c1);
    g_ce_idx[slot] = make_int2(eidx[2 * e], eidx[2 * e + 1]);
    g_ce_u[slot] = make_float4(ediff[3 * e] * inv, ediff[3 * e + 1] * inv,
                               ediff[3 * e + 2] * inv, 0.5f * (c1 + 1.0f));
    g_ce_tr[slot] = make_float2(s1 * inv, 2.0f * c1);
}

// ---------------- SGEMM 128x64x16 (N=384 GEMMs): 8x4/thread, prefetch ----------------
template <int ACT>
__global__ void __launch_bounds__(256)
sgemm128_kernel(int abuf, const float* __restrict__ B,
                const float* __restrict__ bias, int cbuf,
                int M, int N, int K) {
    const float* A = buf_ptr(abuf);
    float* C = buf_ptr(cbuf);

    const int BM = 128, BN = 64, BK = 16;
    __shared__ float As[BK][BM + 4];
    __shared__ float Bs[BK][BN];

    int tid = threadIdx.x;
    int tx = tid & 15;
    int ty = tid >> 4;
    int row0 = blockIdx.y * BM;
    int col0 = blockIdx.x * BN;

    int ar = tid >> 2;
    int ac = (tid & 3) * 4;
    int br = tid >> 4;
    int bc = (tid & 15) * 4;

    bool va0 = (row0 + ar) < M;
    bool va1 = (row0 + ar + 64) < M;
    const float* Ap0 = A + (size_t)(row0 + ar) * K + ac;
    const float* Ap1 = A + (size_t)(row0 + ar + 64) * K + ac;
    const float* Bp = B + (size_t)br * N + col0 + bc;

    unsigned long long acc[8][2];
#pragma unroll
    for (int i = 0; i < 8; i++) { acc[i][0] = 0ull; acc[i][1] = 0ull; }

    const float4 fz = make_float4(0.f, 0.f, 0.f, 0.f);
    float4 a0 = va0 ? *(const float4*)Ap0 : fz;
    float4 a1 = va1 ? *(const float4*)Ap1 : fz;
    float4 b0 = *(const float4*)Bp;

    for (int k0 = 0; k0 < K; k0 += BK) {
        As[ac + 0][ar] = a0.x;
        As[ac + 1][ar] = a0.y;
        As[ac + 2][ar] = a0.z;
        As[ac + 3][ar] = a0.w;
        As[ac + 0][ar + 64] = a1.x;
        As[ac + 1][ar + 64] = a1.y;
        As[ac + 2][ar + 64] = a1.z;
        As[ac + 3][ar + 64] = a1.w;
        *(float4*)&Bs[br][bc] = b0;
        __syncthreads();

        if (k0 + BK < K) {
            int kn = k0 + BK;
            a0 = va0 ? *(const float4*)(Ap0 + kn) : fz;
            a1 = va1 ? *(const float4*)(Ap1 + kn) : fz;
            b0 = *(const float4*)(Bp + (size_t)kn * N);
        }

#pragma unroll
        for (int kk = 0; kk < BK; kk++) {
            float af[8];
            *(float4*)&af[0] = *(const float4*)&As[kk][ty * 8];
            *(float4*)&af[4] = *(const float4*)&As[kk][ty * 8 + 4];
            ulonglong2 bq = *(const ulonglong2*)&Bs[kk][tx * 4];
#pragma unroll
            for (int i = 0; i < 8; i++) {
                unsigned long long ad = dup2(af[i]);
                fma2(acc[i][0], ad, bq.x);
                fma2(acc[i][1], ad, bq.y);
            }
        }
        __syncthreads();
    }

#pragma unroll
    for (int i = 0; i < 8; i++) {
        int r = row0 + ty * 8 + i;
        if (r >= M) continue;
        int c = col0 + tx * 4;
        float4 o;
        unpack2(acc[i][0], o.x, o.y);
        unpack2(acc[i][1], o.z, o.w);
        if (bias) {
            o.x += bias[c + 0];
            o.y += bias[c + 1];
            o.z += bias[c + 2];
            o.w += bias[c + 3];
        }
        if (ACT == 1) {
            o.x = silu_f(o.x);
            o.y = silu_f(o.y);
            o.z = silu_f(o.z);
            o.w = silu_f(o.w);
        }
        *(float4*)&C[(size_t)r * N + c] = o;
    }
}

// ---------------- SGEMM 64x64x16 (N=128 GEMMs): 4x4/thread, prefetch ----------------
template <int ACT>
__global__ void __launch_bounds__(256)
sgemm64_kernel(int abuf, const float* __restrict__ B,
               const float* __restrict__ bias, int cbuf,
               int M, int N, int K) {
    const float* A = buf_ptr(abuf);
    float* C = buf_ptr(cbuf);

    const int BM = 64, BN = 64, BK = 16;
    __shared__ float As[BK][BM + 4];
    __shared__ float Bs[BK][BN];

    int tid = threadIdx.x;
    int tx = tid & 15;
    int ty = tid >> 4;
    int row0 = blockIdx.y * BM;
    int col0 = blockIdx.x * BN;

    int ar = tid >> 2;
    int ac = (tid & 3) * 4;
    int br = tid >> 4;
    int bc = (tid & 15) * 4;

    bool va = (row0 + ar) < M;
    const float* Ap = A + (size_t)(row0 + ar) * K + ac;
    const float* Bp = B + (size_t)br * N + col0 + bc;

    unsigned long long acc[4][2];
#pragma unroll
    for (int i = 0; i < 4; i++) { acc[i][0] = 0ull; acc[i][1] = 0ull; }

    const float4 fz = make_float4(0.f, 0.f, 0.f, 0.f);
    float4 a0 = va ? *(const float4*)Ap : fz;
    float4 b0 = *(const float4*)Bp;

    for (int k0 = 0; k0 < K; k0 += BK) {
        As[ac + 0][ar] = a0.x;
        As[ac + 1][ar] = a0.y;
        As[ac + 2][ar] = a0.z;
        As[ac + 3][ar] = a0.w;
        *(float4*)&Bs[br][bc] = b0;
        __syncthreads();

        if (k0 + BK < K) {
            int kn = k0 + BK;
            a0 = va ? *(const float4*)(Ap + kn) : fz;
            b0 = *(const float4*)(Bp + (size_t)kn * N);
        }

#pragma unroll
        for (int kk = 0; kk < BK; kk++) {
            float af[4];
            *(float4*)af = *(const float4*)&As[kk][ty * 4];
            ulonglong2 bq = *(const ulonglong2*)&Bs[kk][tx * 4];
#pragma unroll
            for (int i = 0; i < 4; i++) {
                unsigned long long ad = dup2(af[i]);
                fma2(acc[i][0], ad, bq.x);
                fma2(acc[i][1], ad, bq.y);
            }
        }
        __syncthreads();
    }

#pragma unroll
    for (int i = 0; i < 4; i++) {
        int r = row0 + ty * 4 + i;
        if (r >= M) continue;
        int c = col0 + tx * 4;
        float4 o;
        unpack2(acc[i][0], o.x, o.y);
        unpack2(acc[i][1], o.z, o.w);
        if (bias) {
            o.x += bias[c + 0];
            o.y += bias[c + 1];
            o.z += bias[c + 2];
            o.w += bias[c + 3];
        }
        if (ACT == 1) {
            o.x = silu_f(o.x);
            o.y = silu_f(o.y);
            o.z = silu_f(o.z);
            o.w = silu_f(o.w);
        }
        *(float4*)&C[(size_t)r * N + c] = o;
    }
}

// ---------------- dual-B SGEMM (BM=128): Uv = v@U, Vv = v@V, shared A tile ----------------
__global__ void __launch_bounds__(256)
sgemm_uv_kernel(const float* __restrict__ B1, const float* __restrict__ B2) {
    const float* A = g_v;
    const int M = NA * 3, N = FF, K = FF;
    const int BM = 128, BN = 64, BK = 16;
    __shared__ float As[BK][BM + 4];
    __shared__ float Bs1[BK][BN];
    __shared__ float Bs2[BK][BN];

    int tid = threadIdx.x;
    int tx = tid & 15;
    int ty = tid >> 4;
    int row0 = blockIdx.y * BM;
    int col0 = blockIdx.x * BN;

    int ar = tid >> 2;
    int ac = (tid & 3) * 4;
    int br = tid >> 4;
    int bc = (tid & 15) * 4;

    bool va0 = (row0 + ar) < M;
    bool va1 = (row0 + ar + 64) < M;
    const float* Ap0 = A + (size_t)(row0 + ar) * K + ac;
    const float* Ap1 = A + (size_t)(row0 + ar + 64) * K + ac;
    const float* Bp1 = B1 + (size_t)br * N + col0 + bc;
    const float* Bp2 = B2 + (size_t)br * N + col0 + bc;

    unsigned long long accU[8][2], accV[8][2];
#pragma unroll
    for (int i = 0; i < 8; i++) {
        accU[i][0] = accU[i][1] = 0ull;
        accV[i][0] = accV[i][1] = 0ull;
    }

    const float4 fz = make_float4(0.f, 0.f, 0.f, 0.f);
    float4 a0 = va0 ? *(const float4*)Ap0 : fz;
    float4 a1 = va1 ? *(const float4*)Ap1 : fz;
    float4 b1 = *(const float4*)Bp1;
    float4 b2 = *(const float4*)Bp2;

    for (int k0 = 0; k0 < K; k0 += BK) {
        As[ac + 0][ar] = a0.x;
        As[ac + 1][ar] = a0.y;
        As[ac + 2][ar] = a0.z;
        As[ac + 3][ar] = a0.w;
        As[ac + 0][ar + 64] = a1.x;
        As[ac + 1][ar + 64] = a1.y;
        As[ac + 2][ar + 64] = a1.z;
        As[ac + 3][ar + 64] = a1.w;
        *(float4*)&Bs1[br][bc] = b1;
        *(float4*)&Bs2[br][bc] = b2;
        __syncthreads();

        if (k0 + BK < K) {
            int kn = k0 + BK;
            a0 = va0 ? *(const float4*)(Ap0 + kn) : fz;
            a1 = va1 ? *(const float4*)(Ap1 + kn) : fz;
            b1 = *(const float4*)(Bp1 + (size_t)kn * N);
            b2 = *(const float4*)(Bp2 + (size_t)kn * N);
        }

#pragma unroll
        for (int kk = 0; kk < BK; kk++) {
            float af[8];
            *(float4*)&af[0] = *(const float4*)&As[kk][ty * 8];
            *(float4*)&af[4] = *(const float4*)&As[kk][ty * 8 + 4];
            ulonglong2 bu = *(const ulonglong2*)&Bs1[kk][tx * 4];
            ulonglong2 bv = *(const ulonglong2*)&Bs2[kk][tx * 4];
#pragma unroll
            for (int i = 0; i < 8; i++) {
                unsigned long long ad = dup2(af[i]);
                fma2(accU[i][0], ad, bu.x);
                fma2(accU[i][1], ad, bu.y);
                fma2(accV[i][0], ad, bv.x);
                fma2(accV[i][1], ad, bv.y);
            }
        }
        __syncthreads();
    }

#pragma unroll
    for (int i = 0; i < 8; i++) {
        int r = row0 + ty * 8 + i;
        if (r >= M) continue;
        int c = col0 + tx * 4;
        float4 ou, ov;
        unpack2(accU[i][0], ou.x, ou.y);
        unpack2(accU[i][1], ou.z, ou.w);
        unpack2(accV[i][0], ov.x, ov.y);
        unpack2(accV[i][1], ov.z, ov.w);
        *(float4*)&g_Uv[(size_t)r * N + c] = ou;
        *(float4*)&g_Vv[(size_t)r * N + c] = ov;
    }
}

// ---------------- edge message kernel: compacted edges, 4 per warp iteration ----------------
__global__ void __launch_bounds__(256, 2)
edge_kernel(const float* __restrict__ fw,   // 20 x 384 (layer slice)
            const float* __restrict__ fb) { // 384
    __shared__ float sfw[NB * 384];
    __shared__ float sfb[384];
    for (int i = threadIdx.x; i < NB * 384; i += blockDim.x) sfw[i] = fw[i];
    for (int i = threadIdx.x; i < 384; i += blockDim.x) sfb[i] = fb[i];
    __syncthreads();

    int lane = threadIdx.x & 31;
    int gw = (blockIdx.x * blockDim.x + threadIdx.x) >> 5;
    int nw = (gridDim.x * blockDim.x) >> 5;
    int nval = g_nval;

    ulonglong2 bg[3];
#pragma unroll
    for (int g = 0; g < 3; g++) bg[g] = *(const ulonglong2*)&sfb[g * 128 + 4 * lane];

    for (int e0 = gw * 4; e0 < nval; e0 += nw * 4) {
        int cnt = nval - e0;
        if (cnt > 4) cnt = 4;

        int dst[4], src[4];
        float4 ue[4];
        float sp[4], sc[4], twoc[4];
#pragma unroll
        for (int j = 0; j < 4; j++) {
            int e = (j < cnt) ? e0 + j : e0;  // clamp: duplicate work discarded later
            int2 ij = g_ce_idx[e];
            dst[j] = ij.x;
            src[j] = ij.y;
            ue[j] = g_ce_u[e];
            float2 tg = g_ce_tr[e];
            sp[j] = 0.0f;
            sc[j] = tg.x;       // sin(x)/dist (scaled recurrence)
            twoc[j] = tg.y;     // 2 cos(x)
        }

        ulonglong2 acc[4][3];
#pragma unroll
        for (int j = 0; j < 4; j++)
#pragma unroll
            for (int g = 0; g < 3; g++) acc[j][g] = bg[g];

#pragma unroll
        for (int b = 0; b < NB; b++) {
            ulonglong2 w0 = *(const ulonglong2*)&sfw[b * 384 + 0 * 128 + 4 * lane];
            ulonglong2 w1 = *(const ulonglong2*)&sfw[b * 384 + 1 * 128 + 4 * lane];
            ulonglong2 w2 = *(const ulonglong2*)&sfw[b * 384 + 2 * 128 + 4 * lane];
#pragma unroll
            for (int j = 0; j < 4; j++) {
                float r = sc[j];
                float sn = twoc[j] * sc[j] - sp[j];
                sp[j] = sc[j];
                sc[j] = sn;
                unsigned long long rd = dup2(r);
                fma2(acc[j][0].x, rd, w0.x);
                fma2(acc[j][0].y, rd, w0.y);
                fma2(acc[j][1].x, rd, w1.x);
                fma2(acc[j][1].y, rd, w1.y);
                fma2(acc[j][2].x, rd, w2.x);
                fma2(acc[j][2].y, rd, w2.y);
            }
        }

#pragma unroll
        for (int j = 0; j < 4; j++) {
            if (j >= cnt) break;
            float ej = ue[j].w;
            float f0[4], f1[4], f2[4];
            unpack2(acc[j][0].x, f0[0], f0[1]);
            unpack2(acc[j][0].y, f0[2], f0[3]);
            unpack2(acc[j][1].x, f1[0], f1[1]);
            unpack2(acc[j][1].y, f1[2], f1[3]);
            unpack2(acc[j][2].x, f2[0], f2[1]);
            unpack2(acc[j][2].y, f2[2], f2[3]);

            const float4* ph4 = (const float4*)(g_phi + (size_t)src[j] * 384);
            const float4* vs4 = (const float4*)(g_vold + (size_t)src[j] * 384);
            float4 pA = ph4[lane];
            float4 pB = ph4[lane + 32];
            float4 pC = ph4[lane + 64];
            float4 vA = vs4[lane];
            float4 vB = vs4[lane + 32];
            float4 vC = vs4[lane + 64];

            float4 gsv, gev, ms;
            gsv.x = f0[0] * ej * pA.x; gsv.y = f0[1] * ej * pA.y;
            gsv.z = f0[2] * ej * pA.z; gsv.w = f0[3] * ej * pA.w;
            gev.x = f1[0] * ej * pB.x; gev.y = f1[1] * ej * pB.y;
            gev.z = f1[2] * ej * pB.z; gev.w = f1[3] * ej * pB.w;
            ms.x = f2[0] * ej * pC.x; ms.y = f2[1] * ej * pC.y;
            ms.z = f2[2] * ej * pC.z; ms.w = f2[3] * ej * pC.w;

            float* sd = g_s + (size_t)dst[j] * 128 + 4 * lane;
            float* vd = g_v + (size_t)dst[j] * 384 + 4 * lane;
            red_add_v4(sd, ms);

            float u0 = ue[j].x, u1 = ue[j].y, u2 = ue[j].z;
            float4 m0, m1, m2;
            m0.x = vA.x * gsv.x + gev.x * u0; m0.y = vA.y * gsv.y + gev.y * u0;
            m0.z = vA.z * gsv.z + gev.z * u0; m0.w = vA.w * gsv.w + gev.w * u0;
            m1.x = vB.x * gsv.x + gev.x * u1; m1.y = vB.y * gsv.y + gev.y * u1;
            m1.z = vB.z * gsv.z + gev.z * u1; m1.w = vB.w * gsv.w + gev.w * u1;
            m2.x = vC.x * gsv.x + gev.x * u2; m2.y = vC.y * gsv.y + gev.y * u2;
            m2.z = vC.z * gsv.z + gev.z * u2; m2.w = vC.w * gsv.w + gev.w * u2;
            red_add_v4(vd, m0);
            red_add_v4(vd + 128, m1);
            red_add_v4(vd + 256, m2);
        }
    }
}

// ---------------- Vn + concat ----------------
__global__ void vncat_kernel() {
    int idx = blockIdx.x * blockDim.x + threadIdx.x;
    if (idx >= NA * FF) return;
    int n = idx >> 7;
    int f = idx & 127;
    float q = 0.0f;
#pragma unroll
    for (int i = 0; i < 3; i++) {
        float d = g_Vv[(size_t)(n * 3 + i) * FF + f];
        q += d * d;
    }
    g_cat[(size_t)n * 256 + f] = g_s[idx];
    g_cat[(size_t)n * 256 + 128 + f] = sqrtf(q);
}

// ---------------- update ----------------
__global__ void update_kernel() {
    int idx = blockIdx.x * blockDim.x + threadIdx.x;
    if (idx >= NA * FF) return;
    int n = idx >> 7;
    int f = idx & 127;
    float avv = g_a[(size_t)n * 384 + f];
    float asv = g_a[(size_t)n * 384 + 128 + f];
    float ass = g_a[(size_t)n * 384 + 256 + f];
    float dot = 0.0f;
#pragma unroll
    for (int i = 0; i < 3; i++) {
        size_t vi = (size_t)(n * 3 + i) * FF + f;
        float uvi = g_Uv[vi];
        float vvi = g_Vv[vi];
        dot += uvi * vvi;
        float nv = g_v[vi] + avv * uvi;
        g_v[vi] = nv;
        g_vold[vi] = nv;
    }
    g_s[idx] += asv * dot + ass;
}

// ---------------- readout ----------------
__global__ void readout_kernel(const float* __restrict__ w1, const float* __restrict__ b1,
                               const float* __restrict__ w2, const float* __restrict__ b2,
                               float* __restrict__ out) {
    __shared__ float sw1[FF * 64];
    __shared__ float sw2[64];
    __shared__ float sb1[64];
    for (int i = threadIdx.x; i < FF * 64; i += blockDim.x) sw1[i] = w1[i];
    if (threadIdx.x < 64) {
        sw2[threadIdx.x] = w2[threadIdx.x];
        sb1[threadIdx.x] = b1[threadIdx.x];
    }
    __syncthreads();

    int wid = threadIdx.x >> 5;
    int lane = threadIdx.x & 31;
    for (int n = blockIdx.x * 8 + wid; n < NA; n += gridDim.x * 8) {
        const float* srow = g_s + (size_t)n * FF;
        float acc0 = sb1[lane];
        float acc1 = sb1[lane + 32];
        for (int f = 0; f < FF; f++) {
            float sv = srow[f];
            acc0 += sv * sw1[f * 64 + lane];
            acc1 += sv * sw1[f * 64 + lane + 32];
        }
        float r = silu_f(acc0) * sw2[lane] + silu_f(acc1) * sw2[lane + 32];
#pragma unroll
        for (int off = 16; off > 0; off >>= 1)
            r += __shfl_down_sync(0xFFFFFFFF, r, off);
        if (lane == 0) out[n] = r + b2[0];
    }
}

// ---------------- launch ----------------
extern "C" void kernel_launch(void* const* d_in, const int* in_sizes, int n_in,
                              void* d_out, int out_size) {
    const int* Z        = (const int*)d_in[0];
    const int* eidx     = (const int*)d_in[1];
    const float* ediff  = (const float*)d_in[2];
    const float* edist  = (const float*)d_in[3];
    const float* emb    = (const float*)d_in[4];
    const float* msg_w1 = (const float*)d_in[5];
    const float* msg_b1 = (const float*)d_in[6];
    const float* msg_w2 = (const float*)d_in[7];
    const float* msg_b2 = (const float*)d_in[8];
    const float* filt_w = (const float*)d_in[9];
    const float* filt_b = (const float*)d_in[10];
    const float* upd_U  = (const float*)d_in[11];
    const float* upd_V  = (const float*)d_in[12];
    const float* upd_w1 = (const float*)d_in[13];
    const float* upd_b1 = (const float*)d_in[14];
    const float* upd_w2 = (const float*)d_in[15];
    const float* upd_b2 = (const float*)d_in[16];
    const float* ro_w1  = (const float*)d_in[17];
    const float* ro_b1  = (const float*)d_in[18];
    const float* ro_w2  = (const float*)d_in[19];
    const float* ro_b2  = (const float*)d_in[20];
    float* out = (float*)d_out;

    const int EL3 = NA * 3 * FF;
    const int GY64  = (NA + 63) / 64;        // 79
    const int GY128 = (NA + 127) / 128;      // 40
    const int GYUV  = (NA * 3 + 127) / 128;  // 118

    init_kernel<<<(EL3 + 255) / 256, 256>>>(emb, Z);
    compact_kernel<<<(NE + 255) / 256, 256>>>(eidx, edist, ediff);

    for (int l = 0; l < 3; l++) {
        sgemm64_kernel<1><<<dim3(2, GY64), 256>>>(
            BUF_S, msg_w1 + (size_t)l * FF * FF, msg_b1 + l * FF, BUF_H, NA, FF, FF);
        sgemm128_kernel<0><<<dim3(6, GY128), 256>>>(
            BUF_H, msg_w2 + (size_t)l * FF * 384, msg_b2 + l * 384, BUF_PHI, NA, 384, FF);

        edge_kernel<<<1184, 256>>>(filt_w + (size_t)l * NB * 384, filt_b + l * 384);

        sgemm_uv_kernel<<<dim3(2, GYUV), 256>>>(
            upd_U + (size_t)l * FF * FF, upd_V + (size_t)l * FF * FF);

        vncat_kernel<<<(NA * FF + 255) / 256, 256>>>();

        sgemm64_kernel<1><<<dim3(2, GY64), 256>>>(
            BUF_CAT, upd_w1 + (size_t)l * 2 * FF * FF, upd_b1 + l * FF, BUF_H, NA, FF, 2 * FF);
        sgemm128_kernel<0><<<dim3(6, GY128), 256>>>(
            BUF_H, upd_w2 + (size_t)l * FF * 384, upd_b2 + l * 384, BUF_A, NA, 384, FF);

        update_kernel<<<(NA * FF + 255) / 256, 256>>>();
    }

    readout_kernel<<<148, 256>>>(ro_w1, ro_b1, ro_w2, ro_b2, out);
}

// round 17
// speedup vs baseline: 1.1257x; 1.0395x over previous
#include <cuda_runtime.h>
#include <math.h>

#define NA 5000
#define NE 100000
#define FF 128
#define NB 20
#define CUTOFF 5.0f

// ---------------- device scratch (no allocations allowed) ----------------
__device__ float g_s[NA * FF];
__device__ float g_v[NA * 3 * FF];
__device__ float g_vold[NA * 3 * FF];
__device__ float g_phi[NA * 3 * FF];
__device__ float g_h[NA * FF];
__device__ float g_Uv[NA * 3 * FF];
__device__ float g_Vv[NA * 3 * FF];
__device__ float g_cat[NA * 2 * FF];
__device__ float g_a[NA * 3 * FF];

// compacted edge arrays (valid edges only)
__device__ int    g_nval;
__device__ int2   g_ce_idx[NE];   // (dst, src)
__device__ float4 g_ce_u[NE];     // (u0, u1, u2, env)
__device__ float2 g_ce_tr[NE];    // (s1*inv, 2*cos(x))  — scaled sine recurrence seeds

#define BUF_S   0
#define BUF_H   1
#define BUF_PHI 2
#define BUF_V   3
#define BUF_UV  4
#define BUF_VV  5
#define BUF_CAT 6
#define BUF_A   7

__device__ __forceinline__ float* buf_ptr(int b) {
    switch (b) {
        case BUF_S:   return g_s;
        case BUF_H:   return g_h;
        case BUF_PHI: return g_phi;
        case BUF_V:   return g_v;
        case BUF_UV:  return g_Uv;
        case BUF_VV:  return g_Vv;
        case BUF_CAT: return g_cat;
        default:      return g_a;
    }
}

__device__ __forceinline__ float silu_f(float x) {
    return x / (1.0f + __expf(-x));
}

// ---- packed fp32x2 helpers ----
__device__ __forceinline__ unsigned long long dup2(float x) {
    unsigned long long r;
    asm("mov.b64 %0, {%1, %1};" : "=l"(r) : "f"(x));
    return r;
}
__device__ __forceinline__ void fma2(unsigned long long& acc, unsigned long long a,
                                     unsigned long long b) {
    asm("fma.rn.f32x2 %0, %1, %2, %0;" : "+l"(acc) : "l"(a), "l"(b));
}
__device__ __forceinline__ void unpack2(unsigned long long p, float& lo, float& hi) {
    asm("mov.b64 {%0, %1}, %2;" : "=f"(lo), "=f"(hi) : "l"(p));
}
__device__ __forceinline__ void red_add_v4(float* p, float4 v) {
    asm volatile("red.global.add.v4.f32 [%0], {%1, %2, %3, %4};"
                 :: "l"(p), "f"(v.x), "f"(v.y), "f"(v.z), "f"(v.w) : "memory");
}

// ---------------- init: s = emb[Z], v = vold = 0, nval = 0 ----------------
__global__ void init_kernel(const float* __restrict__ emb, const int* __restrict__ Z) {
    int idx = blockIdx.x * blockDim.x + threadIdx.x;
    if (idx == 0) g_nval = 0;
    if (idx < NA * 3 * FF) {
        g_v[idx] = 0.0f;
        g_vold[idx] = 0.0f;
    }
    if (idx < NA * FF) {
        int n = idx >> 7;
        int f = idx & 127;
        g_s[idx] = emb[Z[n] * FF + f];
    }
}

// ---------------- compact valid edges + precompute trig/unit/env ----------------
__global__ void compact_kernel(const int* __restrict__ eidx, const float* __restrict__ edist,
                               const float* __restrict__ ediff) {
    int e = blockIdx.x * blockDim.x + threadIdx.x;
    if (e >= NE) return;
    float dist = edist[e];
    if (dist >= CUTOFF) return;
    int slot = atomicAdd(&g_nval, 1);
    float inv = 1.0f / dist;
    float x = dist * (3.14159265358979323846f / CUTOFF);
    float s1, c1;
    __sincosf(x, &s1, &c1);
    g_ce_idx[slot] = make_int2(eidx[2 * e], eidx[2 * e + 1]);
    g_ce_u[slot] = make_float4(ediff[3 * e] * inv, ediff[3 * e + 1] * inv,
                               ediff[3 * e + 2] * inv, 0.5f * (c1 + 1.0f));
    g_ce_tr[slot] = make_float2(s1 * inv, 2.0f * c1);
}

// ---------------- SGEMM 128x64x16 (N=384 GEMMs): 8x4/thread, prefetch ----------------
template <int ACT>
__global__ void __launch_bounds__(256)
sgemm128_kernel(int abuf, const float* __restrict__ B,
                const float* __restrict__ bias, int cbuf,
                int M, int N, int K) {
    const float* A = buf_ptr(abuf);
    float* C = buf_ptr(cbuf);

    const int BM = 128, BN = 64, BK = 16;
    __shared__ float As[BK][BM + 4];
    __shared__ float Bs[BK][BN];

    int tid = threadIdx.x;
    int tx = tid & 15;
    int ty = tid >> 4;
    int row0 = blockIdx.y * BM;
    int col0 = blockIdx.x * BN;

    int ar = tid >> 2;
    int ac = (tid & 3) * 4;
    int br = tid >> 4;
    int bc = (tid & 15) * 4;

    bool va0 = (row0 + ar) < M;
    bool va1 = (row0 + ar + 64) < M;
    const float* Ap0 = A + (size_t)(row0 + ar) * K + ac;
    const float* Ap1 = A + (size_t)(row0 + ar + 64) * K + ac;
    const float* Bp = B + (size_t)br * N + col0 + bc;

    unsigned long long acc[8][2];
#pragma unroll
    for (int i = 0; i < 8; i++) { acc[i][0] = 0ull; acc[i][1] = 0ull; }

    const float4 fz = make_float4(0.f, 0.f, 0.f, 0.f);
    float4 a0 = va0 ? *(const float4*)Ap0 : fz;
    float4 a1 = va1 ? *(const float4*)Ap1 : fz;
    float4 b0 = *(const float4*)Bp;

    for (int k0 = 0; k0 < K; k0 += BK) {
        As[ac + 0][ar] = a0.x;
        As[ac + 1][ar] = a0.y;
        As[ac + 2][ar] = a0.z;
        As[ac + 3][ar] = a0.w;
        As[ac + 0][ar + 64] = a1.x;
        As[ac + 1][ar + 64] = a1.y;
        As[ac + 2][ar + 64] = a1.z;
        As[ac + 3][ar + 64] = a1.w;
        *(float4*)&Bs[br][bc] = b0;
        __syncthreads();

        if (k0 + BK < K) {
            int kn = k0 + BK;
            a0 = va0 ? *(const float4*)(Ap0 + kn) : fz;
            a1 = va1 ? *(const float4*)(Ap1 + kn) : fz;
            b0 = *(const float4*)(Bp + (size_t)kn * N);
        }

#pragma unroll
        for (int kk = 0; kk < BK; kk++) {
            float af[8];
            *(float4*)&af[0] = *(const float4*)&As[kk][ty * 8];
            *(float4*)&af[4] = *(const float4*)&As[kk][ty * 8 + 4];
            ulonglong2 bq = *(const ulonglong2*)&Bs[kk][tx * 4];
#pragma unroll
            for (int i = 0; i < 8; i++) {
                unsigned long long ad = dup2(af[i]);
                fma2(acc[i][0], ad, bq.x);
                fma2(acc[i][1], ad, bq.y);
            }
        }
        __syncthreads();
    }

#pragma unroll
    for (int i = 0; i < 8; i++) {
        int r = row0 + ty * 8 + i;
        if (r >= M) continue;
        int c = col0 + tx * 4;
        float4 o;
        unpack2(acc[i][0], o.x, o.y);
        unpack2(acc[i][1], o.z, o.w);
        if (bias) {
            o.x += bias[c + 0];
            o.y += bias[c + 1];
            o.z += bias[c + 2];
            o.w += bias[c + 3];
        }
        if (ACT == 1) {
            o.x = silu_f(o.x);
            o.y = silu_f(o.y);
            o.z = silu_f(o.z);
            o.w = silu_f(o.w);
        }
        *(float4*)&C[(size_t)r * N + c] = o;
    }
}

// ---------------- SGEMM 64x64x16 (N=128 GEMMs): 4x4/thread, prefetch ----------------
template <int ACT>
__global__ void __launch_bounds__(256)
sgemm64_kernel(int abuf, const float* __restrict__ B,
               const float* __restrict__ bias, int cbuf,
               int M, int N, int K) {
    const float* A = buf_ptr(abuf);
    float* C = buf_ptr(cbuf);

    const int BM = 64, BN = 64, BK = 16;
    __shared__ float As[BK][BM + 4];
    __shared__ float Bs[BK][BN];

    int tid = threadIdx.x;
    int tx = tid & 15;
    int ty = tid >> 4;
    int row0 = blockIdx.y * BM;
    int col0 = blockIdx.x * BN;

    int ar = tid >> 2;
    int ac = (tid & 3) * 4;
    int br = tid >> 4;
    int bc = (tid & 15) * 4;

    bool va = (row0 + ar) < M;
    const float* Ap = A + (size_t)(row0 + ar) * K + ac;
    const float* Bp = B + (size_t)br * N + col0 + bc;

    unsigned long long acc[4][2];
#pragma unroll
    for (int i = 0; i < 4; i++) { acc[i][0] = 0ull; acc[i][1] = 0ull; }

    const float4 fz = make_float4(0.f, 0.f, 0.f, 0.f);
    float4 a0 = va ? *(const float4*)Ap : fz;
    float4 b0 = *(const float4*)Bp;

    for (int k0 = 0; k0 < K; k0 += BK) {
        As[ac + 0][ar] = a0.x;
        As[ac + 1][ar] = a0.y;
        As[ac + 2][ar] = a0.z;
        As[ac + 3][ar] = a0.w;
        *(float4*)&Bs[br][bc] = b0;
        __syncthreads();

        if (k0 + BK < K) {
            int kn = k0 + BK;
            a0 = va ? *(const float4*)(Ap + kn) : fz;
            b0 = *(const float4*)(Bp + (size_t)kn * N);
        }

#pragma unroll
        for (int kk = 0; kk < BK; kk++) {
            float af[4];
            *(float4*)af = *(const float4*)&As[kk][ty * 4];
            ulonglong2 bq = *(const ulonglong2*)&Bs[kk][tx * 4];
#pragma unroll
            for (int i = 0; i < 4; i++) {
                unsigned long long ad = dup2(af[i]);
                fma2(acc[i][0], ad, bq.x);
                fma2(acc[i][1], ad, bq.y);
            }
        }
        __syncthreads();
    }

#pragma unroll
    for (int i = 0; i < 4; i++) {
        int r = row0 + ty * 4 + i;
        if (r >= M) continue;
        int c = col0 + tx * 4;
        float4 o;
        unpack2(acc[i][0], o.x, o.y);
        unpack2(acc[i][1], o.z, o.w);
        if (bias) {
            o.x += bias[c + 0];
            o.y += bias[c + 1];
            o.z += bias[c + 2];
            o.w += bias[c + 3];
        }
        if (ACT == 1) {
            o.x = silu_f(o.x);
            o.y = silu_f(o.y);
            o.z = silu_f(o.z);
            o.w = silu_f(o.w);
        }
        *(float4*)&C[(size_t)r * N + c] = o;
    }
}

// ---------------- dual-B SGEMM (BM=128): Uv = v@U, Vv = v@V, shared A tile ----------------
__global__ void __launch_bounds__(256)
sgemm_uv_kernel(const float* __restrict__ B1, const float* __restrict__ B2) {
    const float* A = g_v;
    const int M = NA * 3, N = FF, K = FF;
    const int BM = 128, BN = 64, BK = 16;
    __shared__ float As[BK][BM + 4];
    __shared__ float Bs1[BK][BN];
    __shared__ float Bs2[BK][BN];

    int tid = threadIdx.x;
    int tx = tid & 15;
    int ty = tid >> 4;
    int row0 = blockIdx.y * BM;
    int col0 = blockIdx.x * BN;

    int ar = tid >> 2;
    int ac = (tid & 3) * 4;
    int br = tid >> 4;
    int bc = (tid & 15) * 4;

    bool va0 = (row0 + ar) < M;
    bool va1 = (row0 + ar + 64) < M;
    const float* Ap0 = A + (size_t)(row0 + ar) * K + ac;
    const float* Ap1 = A + (size_t)(row0 + ar + 64) * K + ac;
    const float* Bp1 = B1 + (size_t)br * N + col0 + bc;
    const float* Bp2 = B2 + (size_t)br * N + col0 + bc;

    unsigned long long accU[8][2], accV[8][2];
#pragma unroll
    for (int i = 0; i < 8; i++) {
        accU[i][0] = accU[i][1] = 0ull;
        accV[i][0] = accV[i][1] = 0ull;
    }

    const float4 fz = make_float4(0.f, 0.f, 0.f, 0.f);
    float4 a0 = va0 ? *(const float4*)Ap0 : fz;
    float4 a1 = va1 ? *(const float4*)Ap1 : fz;
    float4 b1 = *(const float4*)Bp1;
    float4 b2 = *(const float4*)Bp2;

    for (int k0 = 0; k0 < K; k0 += BK) {
        As[ac + 0][ar] = a0.x;
        As[ac + 1][ar] = a0.y;
        As[ac + 2][ar] = a0.z;
        As[ac + 3][ar] = a0.w;
        As[ac + 0][ar + 64] = a1.x;
        As[ac + 1][ar + 64] = a1.y;
        As[ac + 2][ar + 64] = a1.z;
        As[ac + 3][ar + 64] = a1.w;
        *(float4*)&Bs1[br][bc] = b1;
        *(float4*)&Bs2[br][bc] = b2;
        __syncthreads();

        if (k0 + BK < K) {
            int kn = k0 + BK;
            a0 = va0 ? *(const float4*)(Ap0 + kn) : fz;
            a1 = va1 ? *(const float4*)(Ap1 + kn) : fz;
            b1 = *(const float4*)(Bp1 + (size_t)kn * N);
            b2 = *(const float4*)(Bp2 + (size_t)kn * N);
        }

#pragma unroll
        for (int kk = 0; kk < BK; kk++) {
            float af[8];
            *(float4*)&af[0] = *(const float4*)&As[kk][ty * 8];
            *(float4*)&af[4] = *(const float4*)&As[kk][ty * 8 + 4];
            ulonglong2 bu = *(const ulonglong2*)&Bs1[kk][tx * 4];
            ulonglong2 bv = *(const ulonglong2*)&Bs2[kk][tx * 4];
#pragma unroll
            for (int i = 0; i < 8; i++) {
                unsigned long long ad = dup2(af[i]);
                fma2(accU[i][0], ad, bu.x);
                fma2(accU[i][1], ad, bu.y);
                fma2(accV[i][0], ad, bv.x);
                fma2(accV[i][1], ad, bv.y);
            }
        }
        __syncthreads();
    }

#pragma unroll
    for (int i = 0; i < 8; i++) {
        int r = row0 + ty * 8 + i;
        if (r >= M) continue;
        int c = col0 + tx * 4;
        float4 ou, ov;
        unpack2(accU[i][0], ou.x, ou.y);
        unpack2(accU[i][1], ou.z, ou.w);
        unpack2(accV[i][0], ov.x, ov.y);
        unpack2(accV[i][1], ov.z, ov.w);
        *(float4*)&g_Uv[(size_t)r * N + c] = ou;
        *(float4*)&g_Vv[(size_t)r * N + c] = ov;
    }
}

// ---------------- edge message kernel: compacted edges, 4 per warp iteration ----------------
__global__ void __launch_bounds__(256, 2)
edge_kernel(const float* __restrict__ fw,   // 20 x 384 (layer slice)
            const float* __restrict__ fb) { // 384
    __shared__ float sfw[NB * 384];
    __shared__ float sfb[384];
    for (int i = threadIdx.x; i < NB * 384; i += blockDim.x) sfw[i] = fw[i];
    for (int i = threadIdx.x; i < 384; i += blockDim.x) sfb[i] = fb[i];
    __syncthreads();

    int lane = threadIdx.x & 31;
    int gw = (blockIdx.x * blockDim.x + threadIdx.x) >> 5;
    int nw = (gridDim.x * blockDim.x) >> 5;
    int nval = g_nval;

    ulonglong2 bg[3];
#pragma unroll
    for (int g = 0; g < 3; g++) bg[g] = *(const ulonglong2*)&sfb[g * 128 + 4 * lane];

    for (int e0 = gw * 4; e0 < nval; e0 += nw * 4) {
        int cnt = nval - e0;
        if (cnt > 4) cnt = 4;

        int dst[4], src[4];
        float4 ue[4];
        float sp[4], sc[4], twoc[4];
#pragma unroll
        for (int j = 0; j < 4; j++) {
            int e = (j < cnt) ? e0 + j : e0;  // clamp: duplicate work discarded later
            int2 ij = g_ce_idx[e];
            dst[j] = ij.x;
            src[j] = ij.y;
            ue[j] = g_ce_u[e];
            float2 tg = g_ce_tr[e];
            sp[j] = 0.0f;
            sc[j] = tg.x;       // sin(x)/dist (scaled recurrence)
            twoc[j] = tg.y;     // 2 cos(x)
        }

        ulonglong2 acc[4][3];
#pragma unroll
        for (int j = 0; j < 4; j++)
#pragma unroll
            for (int g = 0; g < 3; g++) acc[j][g] = bg[g];

#pragma unroll
        for (int b = 0; b < NB; b++) {
            ulonglong2 w0 = *(const ulonglong2*)&sfw[b * 384 + 0 * 128 + 4 * lane];
            ulonglong2 w1 = *(const ulonglong2*)&sfw[b * 384 + 1 * 128 + 4 * lane];
            ulonglong2 w2 = *(const ulonglong2*)&sfw[b * 384 + 2 * 128 + 4 * lane];
#pragma unroll
            for (int j = 0; j < 4; j++) {
                float r = sc[j];
                float sn = twoc[j] * sc[j] - sp[j];
                sp[j] = sc[j];
                sc[j] = sn;
                unsigned long long rd = dup2(r);
                fma2(acc[j][0].x, rd, w0.x);
                fma2(acc[j][0].y, rd, w0.y);
                fma2(acc[j][1].x, rd, w1.x);
                fma2(acc[j][1].y, rd, w1.y);
                fma2(acc[j][2].x, rd, w2.x);
                fma2(acc[j][2].y, rd, w2.y);
            }
        }

#pragma unroll
        for (int j = 0; j < 4; j++) {
            if (j >= cnt) break;
            float ej = ue[j].w;
            float f0[4], f1[4], f2[4];
            unpack2(acc[j][0].x, f0[0], f0[1]);
            unpack2(acc[j][0].y, f0[2], f0[3]);
            unpack2(acc[j][1].x, f1[0], f1[1]);
            unpack2(acc[j][1].y, f1[2], f1[3]);
            unpack2(acc[j][2].x, f2[0], f2[1]);
            unpack2(acc[j][2].y, f2[2], f2[3]);

            const float4* ph4 = (const float4*)(g_phi + (size_t)src[j] * 384);
            const float4* vs4 = (const float4*)(g_vold + (size_t)src[j] * 384);
            float4 pA = ph4[lane];
            float4 pB = ph4[lane + 32];
            float4 pC = ph4[lane + 64];
            float4 vA = vs4[lane];
            float4 vB = vs4[lane + 32];
            float4 vC = vs4[lane + 64];

            float4 gsv, gev, ms;
            gsv.x = f0[0] * ej * pA.x; gsv.y = f0[1] * ej * pA.y;
            gsv.z = f0[2] * ej * pA.z; gsv.w = f0[3] * ej * pA.w;
            gev.x = f1[0] * ej * pB.x; gev.y = f1[1] * ej * pB.y;
            gev.z = f1[2] * ej * pB.z; gev.w = f1[3] * ej * pB.w;
            ms.x = f2[0] * ej * pC.x; ms.y = f2[1] * ej * pC.y;
            ms.z = f2[2] * ej * pC.z; ms.w = f2[3] * ej * pC.w;

            float* sd = g_s + (size_t)dst[j] * 128 + 4 * lane;
            float* vd = g_v + (size_t)dst[j] * 384 + 4 * lane;
            red_add_v4(sd, ms);

            float u0 = ue[j].x, u1 = ue[j].y, u2 = ue[j].z;
            float4 m0, m1, m2;
            m0.x = vA.x * gsv.x + gev.x * u0; m0.y = vA.y * gsv.y + gev.y * u0;
            m0.z = vA.z * gsv.z + gev.z * u0; m0.w = vA.w * gsv.w + gev.w * u0;
            m1.x = vB.x * gsv.x + gev.x * u1; m1.y = vB.y * gsv.y + gev.y * u1;
            m1.z = vB.z * gsv.z + gev.z * u1; m1.w = vB.w * gsv.w + gev.w * u1;
            m2.x = vC.x * gsv.x + gev.x * u2; m2.y = vC.y * gsv.y + gev.y * u2;
            m2.z = vC.z * gsv.z + gev.z * u2; m2.w = vC.w * gsv.w + gev.w * u2;
            red_add_v4(vd, m0);
            red_add_v4(vd + 128, m1);
            red_add_v4(vd + 256, m2);
        }
    }
}

// ---------------- Vn + concat (float4-vectorized) ----------------
__global__ void vncat_kernel() {
    int idx = blockIdx.x * blockDim.x + threadIdx.x;  // over NA*32
    if (idx >= NA * 32) return;
    int n = idx >> 5;
    int k = (idx & 31) * 4;
    float4 s4 = *(const float4*)&g_s[(size_t)n * 128 + k];
    float4 q = make_float4(0.f, 0.f, 0.f, 0.f);
#pragma unroll
    for (int i = 0; i < 3; i++) {
        float4 d = *(const float4*)&g_Vv[(size_t)(n * 3 + i) * FF + k];
        q.x += d.x * d.x; q.y += d.y * d.y; q.z += d.z * d.z; q.w += d.w * d.w;
    }
    q.x = sqrtf(q.x); q.y = sqrtf(q.y); q.z = sqrtf(q.z); q.w = sqrtf(q.w);
    *(float4*)&g_cat[(size_t)n * 256 + k] = s4;
    *(float4*)&g_cat[(size_t)n * 256 + 128 + k] = q;
}

// ---------------- update (float4-vectorized) ----------------
__global__ void update_kernel() {
    int idx = blockIdx.x * blockDim.x + threadIdx.x;  // over NA*32
    if (idx >= NA * 32) return;
    int n = idx >> 5;
    int k = (idx & 31) * 4;
    float4 avv = *(const float4*)&g_a[(size_t)n * 384 + k];
    float4 asv = *(const float4*)&g_a[(size_t)n * 384 + 128 + k];
    float4 ass = *(const float4*)&g_a[(size_t)n * 384 + 256 + k];
    float4 dot = make_float4(0.f, 0.f, 0.f, 0.f);
#pragma unroll
    for (int i = 0; i < 3; i++) {
        size_t vi = (size_t)(n * 3 + i) * FF + k;
        float4 uv = *(const float4*)&g_Uv[vi];
        float4 vv = *(const float4*)&g_Vv[vi];
        dot.x += uv.x * vv.x; dot.y += uv.y * vv.y;
        dot.z += uv.z * vv.z; dot.w += uv.w * vv.w;
        float4 v4 = *(const float4*)&g_v[vi];
        v4.x += avv.x * uv.x; v4.y += avv.y * uv.y;
        v4.z += avv.z * uv.z; v4.w += avv.w * uv.w;
        *(float4*)&g_v[vi] = v4;
        *(float4*)&g_vold[vi] = v4;
    }
    float4 s4 = *(const float4*)&g_s[(size_t)n * 128 + k];
    s4.x += asv.x * dot.x + ass.x;
    s4.y += asv.y * dot.y + ass.y;
    s4.z += asv.z * dot.z + ass.z;
    s4.w += asv.w * dot.w + ass.w;
    *(float4*)&g_s[(size_t)n * 128 + k] = s4;
}

// ---------------- readout ----------------
__global__ void readout_kernel(const float* __restrict__ w1, const float* __restrict__ b1,
                               const float* __restrict__ w2, const float* __restrict__ b2,
                               float* __restrict__ out) {
    __shared__ float sw1[FF * 64];
    __shared__ float sw2[64];
    __shared__ float sb1[64];
    for (int i = threadIdx.x; i < FF * 64; i += blockDim.x) sw1[i] = w1[i];
    if (threadIdx.x < 64) {
        sw2[threadIdx.x] = w2[threadIdx.x];
        sb1[threadIdx.x] = b1[threadIdx.x];
    }
    __syncthreads();

    int wid = threadIdx.x >> 5;
    int lane = threadIdx.x & 31;
    for (int n = blockIdx.x * 8 + wid; n < NA; n += gridDim.x * 8) {
        const float* srow = g_s + (size_t)n * FF;
        float acc0 = sb1[lane];
        float acc1 = sb1[lane + 32];
        for (int f = 0; f < FF; f++) {
            float sv = srow[f];
            acc0 += sv * sw1[f * 64 + lane];
            acc1 += sv * sw1[f * 64 + lane + 32];
        }
        float r = silu_f(acc0) * sw2[lane] + silu_f(acc1) * sw2[lane + 32];
#pragma unroll
        for (int off = 16; off > 0; off >>= 1)
            r += __shfl_down_sync(0xFFFFFFFF, r, off);
        if (lane == 0) out[n] = r + b2[0];
    }
}

// ---------------- launch ----------------
extern "C" void kernel_launch(void* const* d_in, const int* in_sizes, int n_in,
                              void* d_out, int out_size) {
    const int* Z        = (const int*)d_in[0];
    const int* eidx     = (const int*)d_in[1];
    const float* ediff  = (const float*)d_in[2];
    const float* edist  = (const float*)d_in[3];
    const float* emb    = (const float*)d_in[4];
    const float* msg_w1 = (const float*)d_in[5];
    const float* msg_b1 = (const float*)d_in[6];
    const float* msg_w2 = (const float*)d_in[7];
    const float* msg_b2 = (const float*)d_in[8];
    const float* filt_w = (const float*)d_in[9];
    const float* filt_b = (const float*)d_in[10];
    const float* upd_U  = (const float*)d_in[11];
    const float* upd_V  = (const float*)d_in[12];
    const float* upd_w1 = (const float*)d_in[13];
    const float* upd_b1 = (const float*)d_in[14];
    const float* upd_w2 = (const float*)d_in[15];
    const float* upd_b2 = (const float*)d_in[16];
    const float* ro_w1  = (const float*)d_in[17];
    const float* ro_b1  = (const float*)d_in[18];
    const float* ro_w2  = (const float*)d_in[19];
    const float* ro_b2  = (const float*)d_in[20];
    float* out = (float*)d_out;

    const int EL3 = NA * 3 * FF;
    const int GY64  = (NA + 63) / 64;        // 79
    const int GY128 = (NA + 127) / 128;      // 40
    const int GYUV  = (NA * 3 + 127) / 128;  // 118

    init_kernel<<<(EL3 + 255) / 256, 256>>>(emb, Z);
    compact_kernel<<<(NE + 255) / 256, 256>>>(eidx, edist, ediff);

    for (int l = 0; l < 3; l++) {
        sgemm64_kernel<1><<<dim3(2, GY64), 256>>>(
            BUF_S, msg_w1 + (size_t)l * FF * FF, msg_b1 + l * FF, BUF_H, NA, FF, FF);
        sgemm128_kernel<0><<<dim3(6, GY128), 256>>>(
            BUF_H, msg_w2 + (size_t)l * FF * 384, msg_b2 + l * 384, BUF_PHI, NA, 384, FF);

        edge_kernel<<<592, 256>>>(filt_w + (size_t)l * NB * 384, filt_b + l * 384);

        sgemm_uv_kernel<<<dim3(2, GYUV), 256>>>(
            upd_U + (size_t)l * FF * FF, upd_V + (size_t)l * FF * FF);

        vncat_kernel<<<(NA * 32 + 255) / 256, 256>>>();

        sgemm64_kernel<1><<<dim3(2, GY64), 256>>>(
            BUF_CAT, upd_w1 + (size_t)l * 2 * FF * FF, upd_b1 + l * FF, BUF_H, NA, FF, 2 * FF);
        sgemm128_kernel<0><<<dim3(6, GY128), 256>>>(
            BUF_H, upd_w2 + (size_t)l * FF * 384, upd_b2 + l * 384, BUF_A, NA, 384, FF);

        update_kernel<<<(NA * 32 + 255) / 256, 256>>>();
    }

    readout_kernel<<<148, 256>>>(ro_w1, ro_b1, ro_w2, ro_b2, out);
}